// round 14
// baseline (speedup 1.0000x reference)
#include <cuda_runtime.h>
#include <cuda_fp16.h>
#include <cstdint>
#include <math.h>

#define T_TOK   2048
#define DIM     1024
#define NEXP    8
#define HID     4096
#define TOPK    2
#define MAXROWS (T_TOK * TOPK)   // 4096
#define W1ELEM  ((size_t)NEXP * DIM * HID)   // 33.55M
#define W2ELEM  ((size_t)NEXP * HID * DIM)
#define W2CHUNK 4096                          // 1024-uint4 chunks of W2

// ---------------- scratch (__device__ globals) -------------------------------
__device__ __half g_Hh[(size_t)MAXROWS * HID];   // 32 MB hidden acts (fp16)
__device__ __half g_Uh[(size_t)T_TOK * DIM];     // 4 MB fp16 inputs
__device__ __half g_W1h[W1ELEM];                 // 67 MB fp16 W1 [e][k][n]
__device__ __half g_W2h[W2ELEM];                 // 67 MB fp16 W2 [e][k][n]
__device__ float  g_O[(size_t)MAXROWS * DIM];    // 16 MB expert outputs (K-half 0)
__device__ float  g_O2[(size_t)MAXROWS * DIM];   // 16 MB expert outputs (K-half 1)
__device__ int    g_rowmap[MAXROWS];
__device__ int    g_counts[NEXP];
__device__ int    g_offsets[NEXP + 1];
__device__ int    g_tok_e[T_TOK * TOPK];
__device__ float  g_tok_w[T_TOK * TOPK];
__device__ int    g_tok_slot[T_TOK * TOPK];
__device__ int    g_wq;                          // W2-conversion work queue
__device__ float  g_dummy[1];

// ---------------- helpers ----------------------------------------------------
__device__ __forceinline__ uint32_t smem_u32(const void* p) {
    uint32_t a;
    asm("{ .reg .u64 t; cvta.to.shared.u64 t, %1; cvt.u32.u64 %0, t; }"
        : "=r"(a) : "l"(p));
    return a;
}
__device__ __forceinline__ uint32_t packh2(float a, float b) {
    __half2 h = __floats2half2_rn(a, b);
    return *(uint32_t*)&h;
}

#define CP16(dst, src) \
    asm volatile("cp.async.cg.shared.global [%0], [%1], 16;" :: "r"(dst), "l"(src))
#define CP_COMMIT()  asm volatile("cp.async.commit_group;" ::: "memory")
#define CP_WAIT1()   asm volatile("cp.async.wait_group 1;" ::: "memory")
#define CP_WAITALL() asm volatile("cp.async.wait_all;" ::: "memory")

#define LDSM_X4(r, addr) \
    asm volatile("ldmatrix.sync.aligned.m8n8.x4.shared.b16 {%0,%1,%2,%3}, [%4];" \
        : "=r"((r)[0]), "=r"((r)[1]), "=r"((r)[2]), "=r"((r)[3]) : "r"(addr))

#define LDSM_X4_T(r, addr) \
    asm volatile("ldmatrix.sync.aligned.m8n8.x4.trans.shared.b16 {%0,%1,%2,%3}, [%4];" \
        : "=r"((r)[0]), "=r"((r)[1]), "=r"((r)[2]), "=r"((r)[3]) : "r"(addr))

#define MMA_F16(d, a, b) \
    asm volatile("mma.sync.aligned.m16n8k16.row.col.f32.f16.f16.f32 " \
        "{%0,%1,%2,%3}, {%4,%5,%6,%7}, {%8,%9}, {%0,%1,%2,%3};" \
        : "+f"((d)[0]), "+f"((d)[1]), "+f"((d)[2]), "+f"((d)[3]) \
        : "r"((a)[0]), "r"((a)[1]), "r"((a)[2]), "r"((a)[3]), \
          "r"((b)[0]), "r"((b)[1]))

// ---------------- K0: reset counters + work queue ----------------------------
__global__ void k_init()
{
    if (threadIdx.x < NEXP) g_counts[threadIdx.x] = 0;
    if (threadIdx.x == 31) g_wq = 0;
}

// ---------------- K1: router + u->fp16 + W1->fp16 chunk ----------------------
__global__ void k_router(const float* __restrict__ u,
                         const float* __restrict__ cent,
                         const float* __restrict__ bias,
                         const float* __restrict__ W1)
{
    int t    = blockIdx.x;
    int warp = threadIdx.x >> 5;
    int lane = threadIdx.x & 31;

    const float* ur = u + (size_t)t * DIM;
    const float* cr = cent + (size_t)warp * DIM;

    float s = 0.f;
    #pragma unroll 8
    for (int i = lane; i < DIM; i += 32) s += ur[i] * cr[i];
    #pragma unroll
    for (int o = 16; o; o >>= 1) s += __shfl_xor_sync(0xffffffffu, s, o);

    __shared__ float sc[NEXP];
    if (lane == 0) sc[warp] = s + bias[warp];
    __syncthreads();

    if (threadIdx.x == 0) {
        float m = sc[0];
        #pragma unroll
        for (int e = 1; e < NEXP; e++) m = fmaxf(m, sc[e]);
        float p[NEXP];
        float den = 0.f;
        #pragma unroll
        for (int e = 0; e < NEXP; e++) { p[e] = __expf(sc[e] - m); den += p[e]; }

        int e0 = 0;
        #pragma unroll
        for (int e = 1; e < NEXP; e++) if (p[e] > p[e0]) e0 = e;
        int e1 = (e0 == 0) ? 1 : 0;
        #pragma unroll
        for (int e = 0; e < NEXP; e++) if (e != e0 && p[e] > p[e1]) e1 = e;

        float inv = 1.f / den;
        g_tok_e[t * 2 + 0] = e0;  g_tok_w[t * 2 + 0] = p[e0] * inv;
        g_tok_e[t * 2 + 1] = e1;  g_tok_w[t * 2 + 1] = p[e1] * inv;
        atomicAdd(&g_counts[e0], 1);
        atomicAdd(&g_counts[e1], 1);
    }

    // u row -> fp16 (128 uint4 per token; first 128 threads)
    if (threadIdx.x < 128) {
        const float4* src = (const float4*)ur;
        uint4* dst = (uint4*)(g_Uh + (size_t)t * DIM);
        int j = threadIdx.x;
        float4 a = src[2 * j], b = src[2 * j + 1];
        uint4 o;
        o.x = packh2(a.x, a.y);
        o.y = packh2(a.z, a.w);
        o.z = packh2(b.x, b.y);
        o.w = packh2(b.z, b.w);
        dst[j] = o;
    }

    // W1 chunk -> fp16 (2048 uint4 per CTA, 8 iters x 256 threads)
    {
        const float4* src = (const float4*)W1;
        uint4* dst = (uint4*)g_W1h;
        const size_t b0 = (size_t)t * 2048;
        #pragma unroll
        for (int j = 0; j < 8; j++) {
            size_t idx = b0 + (size_t)j * 256 + threadIdx.x;
            float4 a = src[2 * idx], b = src[2 * idx + 1];
            uint4 o;
            o.x = packh2(a.x, a.y);
            o.y = packh2(a.z, a.w);
            o.z = packh2(b.x, b.y);
            o.w = packh2(b.z, b.w);
            dst[idx] = o;
        }
    }
}

// ---------------- K2: fused offsets + maxvio + scatter (single block) --------
__global__ void k_offscatter(float* __restrict__ maxvio_out)
{
    __shared__ int s_off[NEXP];
    __shared__ int s_cur[NEXP];
    int tid = threadIdx.x;
    if (tid < NEXP) s_cur[tid] = 0;
    if (tid == 0) {
        int off = 0, mx = 0;
        #pragma unroll
        for (int e = 0; e < NEXP; e++) {
            s_off[e] = off;
            g_offsets[e] = off;
            int c = g_counts[e];
            off += c;
            if (c > mx) mx = c;
        }
        g_offsets[NEXP] = off;
        const float perfect = (float)(TOPK * T_TOK) / (float)NEXP;
        *maxvio_out = ((float)mx - perfect) / perfect;
    }
    __syncthreads();
    for (int t = tid; t < T_TOK; t += blockDim.x) {
        #pragma unroll
        for (int k = 0; k < TOPK; k++) {
            int e = g_tok_e[t * 2 + k];
            int slot = s_off[e] + atomicAdd(&s_cur[e], 1);
            g_rowmap[slot] = t;
            g_tok_slot[t * 2 + k] = slot;
        }
    }
}

// ---------------- fp16 mma.sync grouped GEMM ---------------------------------
// Block 128x128, BK=64, 3-stage cp.async, 8 warps (2m x 4n), warp tile 64x32.
// IS_G2 == 0: working CTAs compute g_Hh = fp16(relu(A @ W1h + b1));
//             routing-IDLE CTAs drain the W2 fp32->fp16 conversion queue.
// IS_G2 == 1: K split 2 via grid.y = (n-tile 0..7, khalf 0..1) -> g_O / g_O2.
template<int IS_G2>
__global__ __launch_bounds__(256, 2) void k_gemm_f16(
    const __half* __restrict__ Aglob,
    const __half* __restrict__ Wglob,
    const float* __restrict__ bglob,
    const float* __restrict__ W2src)
{
    constexpr int BM = 128, BN = 128, BK = 64, ST = 3;
    constexpr int LDA = BK + 8;               // 72 halves
    constexpr int LDB = BN + 8;               // 136 halves
    constexpr int NLD   = IS_G2 ? DIM : HID;
    constexpr int KTOT  = IS_G2 ? HID : DIM;
    constexpr int KCH   = IS_G2 ? (HID / 2 / BK) : (DIM / BK);   // 32 : 16
    constexpr int ALDIM = IS_G2 ? HID : DIM;
    constexpr int ASZ = BM * LDA * 2;         // 18432 B per A stage
    constexpr int BSZ = BK * LDB * 2;         // 17408 B per B stage
    constexpr int OFF_A = 512;
    constexpr int OFF_B = OFF_A + ST * ASZ;

    extern __shared__ char smem[];
    float* s_bias = (float*)smem;

    const int e    = blockIdx.z;
    const int base = g_offsets[e];
    const int cnt  = g_offsets[e + 1] - base;
    const int m0   = blockIdx.x * BM;
    const int tid  = threadIdx.x;

    if (m0 >= cnt) {
        // -------- routing-idle CTA: drain the W2 conversion queue (G1 only) --
        if (!IS_G2) {
            __shared__ int s_chunk;
            const float4* src = (const float4*)W2src;
            uint4*        dst = (uint4*)g_W2h;
            for (;;) {
                if (tid == 0) s_chunk = atomicAdd(&g_wq, 1);
                __syncthreads();
                int ch = s_chunk;
                __syncthreads();
                if (ch >= W2CHUNK) break;
                const size_t b0 = (size_t)ch * 1024;
                #pragma unroll
                for (int j = 0; j < 4; j++) {
                    size_t idx = b0 + (size_t)j * 256 + tid;
                    float4 a = src[2 * idx], b = src[2 * idx + 1];
                    uint4 o;
                    o.x = packh2(a.x, a.y);
                    o.y = packh2(a.z, a.w);
                    o.z = packh2(b.x, b.y);
                    o.w = packh2(b.z, b.w);
                    dst[idx] = o;
                }
            }
        }
        return;
    }

    const int n0 = (IS_G2 ? (blockIdx.y & 7) : blockIdx.y) * BN;
    const int kbase = IS_G2 ? ((blockIdx.y >> 3) * (HID / 2)) : 0;

    const uint32_t sb = smem_u32(smem);
    const int lane = tid & 31, wid = tid >> 5;
    const int wm = wid & 1, wn = wid >> 1;
    const int g = lane >> 2, tg = lane & 3;

    const __half* W = Wglob + (size_t)e * (size_t)KTOT * NLD;

    if (!IS_G2 && tid < BN) s_bias[tid] = bglob[(size_t)e * NLD + n0 + tid];

    // cp.async slots: A — 128 rows x 8 16B-units = 1024 -> 4/thread
    const __half* asrc[4];
    uint32_t      adst[4];
    #pragma unroll
    for (int j = 0; j < 4; j++) {
        int idx = tid + 256 * j;
        int r = idx >> 3, kq = idx & 7;
        int slot = base + m0 + r;
        if (slot > MAXROWS - 1) slot = MAXROWS - 1;
        if (IS_G2) asrc[j] = Aglob + (size_t)slot * ALDIM + kbase + kq * 8;
        else       asrc[j] = Aglob + (size_t)g_rowmap[slot] * ALDIM + kq * 8;
        adst[j] = sb + OFF_A + r * (LDA * 2) + kq * 16;
    }
    // cp.async slots: B — 64 k-rows x 16 16B-units = 1024 -> 4/thread
    const __half* bsrc[4];
    uint32_t      bdst[4];
    #pragma unroll
    for (int j = 0; j < 4; j++) {
        int idx = tid + 256 * j;
        int k = idx >> 4, nq = idx & 15;
        bsrc[j] = W + (size_t)(kbase + k) * NLD + n0 + nq * 8;
        bdst[j] = sb + OFF_B + k * (LDB * 2) + nq * 16;
    }

    // ldmatrix A bases
    uint32_t amat[4];
    {
        int sector = lane >> 3, rowin = lane & 7;
        #pragma unroll
        for (int mi = 0; mi < 4; mi++) {
            int rloc = wm * 64 + mi * 16 + (sector & 1) * 8 + rowin;
            amat[mi] = sb + OFF_A + rloc * (LDA * 2) + (sector >> 1) * 16;
        }
    }
    // ldmatrix.trans B bases
    uint32_t bmat[2];
    {
        int sector = lane >> 3, rowin = lane & 7;
        #pragma unroll
        for (int n2 = 0; n2 < 2; n2++) {
            int krow = (sector & 1) * 8 + rowin;
            int ncol = wn * 32 + n2 * 16 + (sector >> 1) * 8;
            bmat[n2] = sb + OFF_B + krow * (LDB * 2) + ncol * 2;
        }
    }

    float acc[4][4][4] = {};

    // prologue: prefetch chunks 0 and 1
    #pragma unroll
    for (int pc = 0; pc < ST - 1; pc++) {
        const int k0 = pc * BK;
        #pragma unroll
        for (int j = 0; j < 4; j++) CP16(adst[j] + pc * ASZ, asrc[j] + k0);
        #pragma unroll
        for (int j = 0; j < 4; j++) CP16(bdst[j] + pc * BSZ, bsrc[j] + (size_t)k0 * NLD);
        CP_COMMIT();
    }

    for (int c = 0; c < KCH; c++) {
        CP_WAIT1();
        __syncthreads();

        const int wb = (c + ST - 1) % ST;
        if (c + ST - 1 < KCH) {
            const int k0 = (c + ST - 1) * BK;
            #pragma unroll
            for (int j = 0; j < 4; j++) CP16(adst[j] + wb * ASZ, asrc[j] + k0);
            #pragma unroll
            for (int j = 0; j < 4; j++) CP16(bdst[j] + wb * BSZ, bsrc[j] + (size_t)k0 * NLD);
        }
        CP_COMMIT();

        const int buf = c % ST;
        const uint32_t aoff = (uint32_t)(buf * ASZ);
        const uint32_t boff = (uint32_t)(buf * BSZ);

        #pragma unroll
        for (int ks = 0; ks < 4; ks++) {
            uint32_t au[4][4], br[2][4];
            #pragma unroll
            for (int mi = 0; mi < 4; mi++)
                LDSM_X4(au[mi], amat[mi] + aoff + (uint32_t)(ks * 32));
            #pragma unroll
            for (int n2 = 0; n2 < 2; n2++)
                LDSM_X4_T(br[n2], bmat[n2] + boff + (uint32_t)(ks * 16 * LDB * 2));
            #pragma unroll
            for (int mi = 0; mi < 4; mi++)
                #pragma unroll
                for (int ni = 0; ni < 4; ni++)
                    MMA_F16(acc[mi][ni], au[mi], &br[ni >> 1][(ni & 1) * 2]);
        }
    }
    CP_WAITALL();

    // ---------------- epilogue ----------------
    float* Obuf = (IS_G2 && (blockIdx.y >> 3)) ? g_O2 : g_O;
    #pragma unroll
    for (int mi = 0; mi < 4; mi++) {
        #pragma unroll
        for (int half = 0; half < 2; half++) {
            const int rl = wm * 64 + mi * 16 + half * 8 + g;
            if ((m0 + rl) >= cnt) continue;
            const int slot = base + m0 + rl;
            if (IS_G2) {
                float* orow = Obuf + (size_t)slot * DIM + n0;
                #pragma unroll
                for (int ni = 0; ni < 4; ni++) {
                    const int cl = wn * 32 + ni * 8 + tg * 2;
                    float2 v;
                    v.x = acc[mi][ni][half * 2 + 0];
                    v.y = acc[mi][ni][half * 2 + 1];
                    *(float2*)(orow + cl) = v;
                }
            } else {
                __half* hrow = g_Hh + (size_t)slot * HID + n0;
                #pragma unroll
                for (int ni = 0; ni < 4; ni++) {
                    const int cl = wn * 32 + ni * 8 + tg * 2;
                    float vx = fmaxf(acc[mi][ni][half * 2 + 0] + s_bias[cl], 0.f);
                    float vy = fmaxf(acc[mi][ni][half * 2 + 1] + s_bias[cl + 1], 0.f);
                    *(__half2*)(hrow + cl) = __floats2half2_rn(vx, vy);
                }
            }
        }
    }
}

// ---------------- K5: combine out[t] = sum_k w_k * (oA_k + oB_k + b2[e_k]) ---
__global__ void k_combine(const float* __restrict__ b2, float* __restrict__ out)
{
    int t = blockIdx.x;
    int d = threadIdx.x * 4;
    int e0 = g_tok_e[t * 2], e1 = g_tok_e[t * 2 + 1];
    float w0 = g_tok_w[t * 2], w1 = g_tok_w[t * 2 + 1];
    int s0 = g_tok_slot[t * 2], s1 = g_tok_slot[t * 2 + 1];

    float4 a0 = *(const float4*)(g_O  + (size_t)s0 * DIM + d);
    float4 b0 = *(const float4*)(g_O2 + (size_t)s0 * DIM + d);
    float4 a1 = *(const float4*)(g_O  + (size_t)s1 * DIM + d);
    float4 b1v = *(const float4*)(g_O2 + (size_t)s1 * DIM + d);
    float4 c0 = *(const float4*)(b2 + (size_t)e0 * DIM + d);
    float4 c1 = *(const float4*)(b2 + (size_t)e1 * DIM + d);

    float4 r;
    r.x = w0 * (a0.x + b0.x + c0.x) + w1 * (a1.x + b1v.x + c1.x);
    r.y = w0 * (a0.y + b0.y + c0.y) + w1 * (a1.y + b1v.y + c1.y);
    r.z = w0 * (a0.z + b0.z + c0.z) + w1 * (a1.z + b1v.z + c1.z);
    r.w = w0 * (a0.w + b0.w + c0.w) + w1 * (a1.w + b1v.w + c1.w);
    *(float4*)(out + (size_t)t * DIM + d) = r;
}

// ---------------- launch -----------------------------------------------------
extern "C" void kernel_launch(void* const* d_in, const int* in_sizes, int n_in,
                              void* d_out, int out_size)
{
    const float* u    = (const float*)d_in[0];
    const float* cent = (const float*)d_in[1];
    const float* bias = (const float*)d_in[2];
    const float* W1   = (const float*)d_in[3];
    const float* b1   = (const float*)d_in[4];
    const float* W2   = (const float*)d_in[5];
    const float* b2   = (const float*)d_in[6];
    float* out = (float*)d_out;

    float* maxvio_ptr;
    if (out_size > T_TOK * DIM) {
        maxvio_ptr = out + (size_t)T_TOK * DIM;
    } else {
        cudaGetSymbolAddress((void**)&maxvio_ptr, g_dummy);
    }
    __half* uh;   cudaGetSymbolAddress((void**)&uh,  g_Uh);
    __half* hh;   cudaGetSymbolAddress((void**)&hh,  g_Hh);
    __half* w1h;  cudaGetSymbolAddress((void**)&w1h, g_W1h);
    __half* w2h;  cudaGetSymbolAddress((void**)&w2h, g_W2h);

    const int SMEM = 512 + 3 * 18432 + 3 * 17408;   // 108032 B
    cudaFuncSetAttribute(k_gemm_f16<0>, cudaFuncAttributeMaxDynamicSharedMemorySize, SMEM);
    cudaFuncSetAttribute(k_gemm_f16<1>, cudaFuncAttributeMaxDynamicSharedMemorySize, SMEM);

    k_init<<<1, 32>>>();                                             // idx 0
    k_router<<<T_TOK, 256>>>(u, cent, bias, W1);                     // idx 1
    k_offscatter<<<1, 1024>>>(maxvio_ptr);                           // idx 2
    // gemm1: working CTAs compute; idle CTAs convert W2 via queue
    k_gemm_f16<0><<<dim3(16, HID / 128, NEXP), 256, SMEM>>>(uh, w1h, b1, W2);  // idx 3
    // gemm2: grid.y packs (8 n-tiles, 2 K-halves)
    k_gemm_f16<1><<<dim3(16, 16, NEXP), 256, SMEM>>>(hh, w2h, b2, nullptr);    // idx 4
    k_combine<<<T_TOK, 256>>>(b2, out);                              // idx 5
}